// round 14
// baseline (speedup 1.0000x reference)
#include <cuda_runtime.h>
#include <cuda_bf16.h>
#include <cstdint>
#include <cstddef>

// Problem constants
#define NB 16
#define NT 1024
#define ND 256
// DS = 4

#define BM 128
#define LDSK 136       // bf16 elems per A/B smem row for K=128 chunk (272B, odd 16B stride -> ldmatrix conflict-free)
#define GS_STRIDE 130  // bf16 stride of G staging tile (odd word stride -> conflict-free column reads)

#define GRAM_SMEM (2 * 128 * LDSK * 2)   // 69632 B (~68 KB) -> 2 CTAs/SM

#define NTILE (NT / BM)                 // 8
#define NPAIR (NTILE * (NTILE + 1) / 2) // 36
#define NSTREAM_CTA 2048                // 8 warps/CTA, 1 (b,t) row per warp

// Stream kernel smem: gt ring 8 warps x 4 stages x 128 float4 = 64 KB, G 16 KB
#define STREAM_SMEM (65536 + 16384)

// Scratch (no allocations allowed -> __device__ globals)
__device__ __align__(16) __nv_bfloat16 g_zbf[NB * NT * ND];        // 8.4 MB
__device__ __align__(16) __nv_bfloat16 g_G[(size_t)NB * NT * NT];  // 33.5 MB
__device__ float  g_z2[NB * NT];
__device__ double g_partial[NSTREAM_CTA];
__device__ unsigned int g_count;   // zero-init; self-resets each run (graph-replay safe)

// pair p -> (i,j), i<=j, over 8 tiles
__constant__ int PAIR_I[NPAIR] = {0,0,0,0,0,0,0,0, 1,1,1,1,1,1,1, 2,2,2,2,2,2,
                                  3,3,3,3,3, 4,4,4,4, 5,5,5, 6,6, 7};
__constant__ int PAIR_J[NPAIR] = {0,1,2,3,4,5,6,7, 1,2,3,4,5,6,7, 2,3,4,5,6,7,
                                  3,4,5,6,7, 4,5,6,7, 5,6,7, 6,7, 7};

#define CP_ASYNC16(daddr, src) \
    asm volatile("cp.async.cg.shared.global [%0], [%1], 16;" :: "r"(daddr), "l"(src))
#define CP_COMMIT() asm volatile("cp.async.commit_group;" ::: "memory")
#define CP_WAIT(n)  asm volatile("cp.async.wait_group %0;" :: "n"(n) : "memory")

// ---------------------------------------------------------------------------
// Kernel 0 (R1-proven): z -> bf16 + per-row sum of squares. 2 rows/warp.
// ---------------------------------------------------------------------------
__global__ void prep_kernel(const float* __restrict__ z) {
    const int warp = blockIdx.x * 8 + (threadIdx.x >> 5);
    const int lane = threadIdx.x & 31;
    const int row0 = warp * 2;

    const float4* zr0 = reinterpret_cast<const float4*>(z) + (size_t)row0 * (ND / 4);
    const float4* zr1 = zr0 + (ND / 4);
    float4 a0 = zr0[lane];
    float4 a1 = zr0[lane + 32];
    float4 b0 = zr1[lane];
    float4 b1 = zr1[lane + 32];

    float s0 = a0.x*a0.x + a0.y*a0.y + a0.z*a0.z + a0.w*a0.w
             + a1.x*a1.x + a1.y*a1.y + a1.z*a1.z + a1.w*a1.w;
    float s1 = b0.x*b0.x + b0.y*b0.y + b0.z*b0.z + b0.w*b0.w
             + b1.x*b1.x + b1.y*b1.y + b1.z*b1.z + b1.w*b1.w;
    #pragma unroll
    for (int o = 16; o; o >>= 1) {
        s0 += __shfl_xor_sync(0xffffffffu, s0, o);
        s1 += __shfl_xor_sync(0xffffffffu, s1, o);
    }
    if (lane == 0) { g_z2[row0] = s0; g_z2[row0 + 1] = s1; }

    uint2* d0 = reinterpret_cast<uint2*>(g_zbf + (size_t)row0 * ND);
    uint2* d1 = d0 + (ND / 4);
    auto pack = [](float4 v) {
        __nv_bfloat162 lo = __floats2bfloat162_rn(v.x, v.y);
        __nv_bfloat162 hi = __floats2bfloat162_rn(v.z, v.w);
        uint2 p;
        p.x = *reinterpret_cast<uint32_t*>(&lo);
        p.y = *reinterpret_cast<uint32_t*>(&hi);
        return p;
    };
    d0[lane]      = pack(a0);
    d0[lane + 32] = pack(a1);
    d1[lane]      = pack(b0);
    d1[lane + 32] = pack(b1);
}

// ---------------------------------------------------------------------------
// gram_kernel (unchanged, proven): one CTA per (batch, tile pair i<=j).
// ---------------------------------------------------------------------------
#define LDSM4(r0, r1, r2, r3, addr)                                              \
    asm volatile("ldmatrix.sync.aligned.m8n8.x4.shared.b16 {%0,%1,%2,%3}, [%4];" \
                 : "=r"(r0), "=r"(r1), "=r"(r2), "=r"(r3) : "r"(addr))

#define MMA16816(d, a, b0r, b1r)                                                 \
    asm volatile("mma.sync.aligned.m16n8k16.row.col.f32.bf16.bf16.f32 "          \
                 "{%0,%1,%2,%3}, {%4,%5,%6,%7}, {%8,%9}, {%0,%1,%2,%3};"         \
                 : "+f"(d[0]), "+f"(d[1]), "+f"(d[2]), "+f"(d[3])                \
                 : "r"(a[0]), "r"(a[1]), "r"(a[2]), "r"(a[3]), "r"(b0r), "r"(b1r))

__global__ void __launch_bounds__(256, 2)
gram_kernel() {
    extern __shared__ __align__(16) char sm[];
    __nv_bfloat16* As = reinterpret_cast<__nv_bfloat16*>(sm);
    __nv_bfloat16* Bs = reinterpret_cast<__nv_bfloat16*>(sm + 128 * LDSK * 2);
    __nv_bfloat16* Gst = reinterpret_cast<__nv_bfloat16*>(sm);  // overlays A after GEMM

    const int bb = blockIdx.z;
    const int ti = PAIR_I[blockIdx.x];
    const int tj = PAIR_J[blockIdx.x];
    const int tid = threadIdx.x;
    const int lane = tid & 31;
    const int wid  = tid >> 5;

    const int wm = (wid & 3) * 32;
    const int wn = (wid >> 2) * 64;

    float acc[2][8][4];
    #pragma unroll
    for (int mi = 0; mi < 2; mi++)
        #pragma unroll
        for (int ni = 0; ni < 8; ni++)
            #pragma unroll
            for (int r = 0; r < 4; r++) acc[mi][ni][r] = 0.f;

    const uint32_t aBase = (uint32_t)__cvta_generic_to_shared(As);
    const uint32_t bBase = (uint32_t)__cvta_generic_to_shared(Bs);
    const uint32_t aAddr0 = aBase + (((wm + (lane & 15)) * LDSK + (lane >> 4) * 8)) * 2;
    const uint32_t bAddr0 = bBase + (((wn + (lane & 7) + ((lane >> 4) << 3)) * LDSK
                                     + ((lane >> 3) & 1) * 8)) * 2;

    const int4* gzt = reinterpret_cast<const int4*>(g_zbf + ((size_t)bb * NT + ti * BM) * ND);
    const int4* gzs = reinterpret_cast<const int4*>(g_zbf + ((size_t)bb * NT + tj * BM) * ND);

    #pragma unroll
    for (int kc = 0; kc < 2; kc++) {
        #pragma unroll
        for (int i = 0; i < 8; i++) {
            int idx = tid + i * 256;          // 0..2047
            int r = idx >> 4, c = idx & 15;
            *reinterpret_cast<int4*>(As + r * LDSK + c * 8) = gzt[r * 32 + kc * 16 + c];
            *reinterpret_cast<int4*>(Bs + r * LDSK + c * 8) = gzs[r * 32 + kc * 16 + c];
        }
        __syncthreads();

        #pragma unroll
        for (int kk = 0; kk < 8; kk++) {
            uint32_t a[2][4];
            #pragma unroll
            for (int mi = 0; mi < 2; mi++) {
                uint32_t addr = aAddr0 + (uint32_t)(mi * 16 * LDSK * 2) + (uint32_t)(kk * 32);
                LDSM4(a[mi][0], a[mi][1], a[mi][2], a[mi][3], addr);
            }
            uint32_t bf[8][2];
            #pragma unroll
            for (int nj = 0; nj < 4; nj++) {
                uint32_t addr = bAddr0 + (uint32_t)(nj * 16 * LDSK * 2) + (uint32_t)(kk * 32);
                uint32_t r0, r1, r2, r3;
                LDSM4(r0, r1, r2, r3, addr);
                bf[2 * nj][0] = r0;     bf[2 * nj][1] = r1;
                bf[2 * nj + 1][0] = r2; bf[2 * nj + 1][1] = r3;
            }
            #pragma unroll
            for (int mi = 0; mi < 2; mi++)
                #pragma unroll
                for (int ni = 0; ni < 8; ni++)
                    MMA16816(acc[mi][ni], a[mi], bf[ni][0], bf[ni][1]);
        }
        __syncthreads();
    }

    // ---- write G(ti,tj) rows from fragments; stage for transpose ----
    const int rowc = lane >> 2;
    const int colc = (lane & 3) * 2;
    #pragma unroll
    for (int mi = 0; mi < 2; mi++)
        #pragma unroll
        for (int h = 0; h < 2; h++) {
            const int row = wm + mi * 16 + rowc + h * 8;
            #pragma unroll
            for (int ni = 0; ni < 8; ni++) {
                const int col = wn + ni * 8 + colc;
                __nv_bfloat162 v = __floats2bfloat162_rn(acc[mi][ni][h * 2 + 0],
                                                         acc[mi][ni][h * 2 + 1]);
                *reinterpret_cast<__nv_bfloat162*>(
                    g_G + ((size_t)(bb * NT + ti * BM + row)) * NT + tj * BM + col) = v;
                if (ti != tj)
                    *reinterpret_cast<__nv_bfloat162*>(Gst + row * GS_STRIDE + col) = v;
            }
        }

    // ---- transpose write G(tj,ti) from staged tile ----
    if (ti != tj) {
        __syncthreads();
        #pragma unroll
        for (int i = 0; i < 8; i++) {
            int idx = tid + i * 256;          // 0..2047
            int rp = idx >> 4, c16 = idx & 15;
            __align__(16) __nv_bfloat16 v[8];
            #pragma unroll
            for (int k = 0; k < 8; k++)
                v[k] = Gst[(c16 * 8 + k) * GS_STRIDE + rp];
            *reinterpret_cast<uint4*>(
                g_G + ((size_t)(bb * NT + tj * BM + rp)) * NT + ti * BM + c16 * 8)
                = *reinterpret_cast<uint4*>(v);
        }
    }
}

// ---------------------------------------------------------------------------
// stream_kernel: cp.async deep-pipelined streamer + smem G + fused finalize.
// Warp owns one (b,t) row (16 KB gt, 2 KB G).
//   gt: 8 stages of 2KB/warp through a 4-slot smem ring via cp.async.cg
//       (prologue 3 stages; steady state: wait_group 2 -> process -> issue+commit).
//       In-flight bytes live in smem, not registers -> deep MLP at low reg count.
//   G:  staged once into smem (coalesced uint4), read via LDS.U16.
// Element order identical to R13 -> bit-identical result.
// ---------------------------------------------------------------------------
__global__ void __launch_bounds__(256)
stream_kernel(const float* __restrict__ gt, const float* __restrict__ sigma,
              float* __restrict__ out) {
    extern __shared__ __align__(16) char dsm[];
    float4* sGT = reinterpret_cast<float4*>(dsm);                              // [8][4][128]
    unsigned short* sG = reinterpret_cast<unsigned short*>(dsm + 65536);       // [8][1024]

    const int tid = threadIdx.x;
    const int lane = tid & 31;
    const int wid  = tid >> 5;
    const int bt = blockIdx.x * 8 + wid;      // 0..16383
    const int b = bt >> 10, t = bt & 1023;

    const float sg0 = sigma[0], sg1 = sigma[1], sg2 = sigma[2], sg3 = sigma[3];
    const float inv0 = 1.0f / (2.0f * sg0 * sg0);
    const float inv1 = 1.0f / (2.0f * sg1 * sg1);
    const float inv2 = 1.0f / (2.0f * sg2 * sg2);
    const float inv3 = 1.0f / (2.0f * sg3 * sg3);

    const size_t rowbase = ((size_t)b * NT + t) * NT;
    const float4* gp = reinterpret_cast<const float4*>(gt) + rowbase;
    const float z2t = g_z2[b * NT + t];

    float4* wGT = sGT + wid * 4 * 128;
    unsigned short* wG = sG + wid * 1024;

    // ---- stage this warp's G row (2 KB) into smem, coalesced ----
    {
        const uint4* Gv4 = reinterpret_cast<const uint4*>(g_G + rowbase);
        #pragma unroll
        for (int it = 0; it < 4; it++)
            reinterpret_cast<uint4*>(wG)[lane + it * 32] = Gv4[lane + it * 32];
    }

    // ---- cp.async pipeline over 8 stages (2 KB each) ----
    auto issue_stage = [&](int s) {
        #pragma unroll
        for (int it = 0; it < 4; it++) {
            uint32_t daddr = (uint32_t)__cvta_generic_to_shared(
                &wGT[(s & 3) * 128 + it * 32 + lane]);
            CP_ASYNC16(daddr, gp + s * 128 + it * 32 + lane);
        }
    };
    issue_stage(0); CP_COMMIT();
    issue_stage(1); CP_COMMIT();
    issue_stage(2); CP_COMMIT();

    float part = 0.f;
    for (int s = 0; s < 8; s++) {
        CP_WAIT(2);     // every iter commits exactly one group -> stage s complete
        #pragma unroll
        for (int it = 0; it < 4; it++) {
            float4 g = wGT[(s & 3) * 128 + it * 32 + lane];
            const int e = s * 4 + it;    // warp-iter 0..31, same order as R13
            float q = g.x * g.x * inv0 + g.y * g.y * inv1
                    + g.z * g.z * inv2 + g.w * g.w * inv3;
            float w = __expf(q);
            unsigned short Gq = wG[lane + e * 32];
            float Gv = __bfloat162float(*reinterpret_cast<__nv_bfloat16*>(&Gq));
            part += w * (z2t - Gv);
        }
        if (s + 3 < 8) issue_stage(s + 3);
        CP_COMMIT();    // empty group when no issue: keeps wait_group arithmetic uniform
    }

    // ---- CTA reduction (deterministic) ----
    #pragma unroll
    for (int o = 16; o; o >>= 1) part += __shfl_xor_sync(0xffffffffu, part, o);
    __shared__ double red[8];
    if (lane == 0) red[wid] = (double)part;
    __syncthreads();
    if (tid == 0) {
        double ssum = 0.0;
        #pragma unroll
        for (int i = 0; i < 8; i++) ssum += red[i];
        g_partial[blockIdx.x] = ssum;
    }

    // ---- fused finalize: last CTA reduces all partials in fixed order ----
    __shared__ bool isLast;
    __threadfence();
    if (tid == 0) {
        unsigned int c = atomicAdd(&g_count, 1u);
        isLast = (c == (unsigned int)(gridDim.x - 1));
    }
    __syncthreads();
    if (isLast) {
        __shared__ double fred[256];
        double v = 0.0;
        for (int i = tid; i < NSTREAM_CTA; i += 256) v += g_partial[i];
        fred[tid] = v;
        __syncthreads();
        for (int off = 128; off; off >>= 1) {
            if (tid < off) fred[tid] += fred[tid + off];
            __syncthreads();
        }
        if (tid == 0) {
            out[0] = (float)(fred[0] * (2.0 / ((double)NB * (double)NT * (double)NT)));
            g_count = 0;   // reset for next graph replay
        }
    }
}

// ---------------------------------------------------------------------------
extern "C" void kernel_launch(void* const* d_in, const int* in_sizes, int n_in,
                              void* d_out, int out_size) {
    const float* z     = (const float*)d_in[0];  // [16,1024,256]
    const float* gt    = (const float*)d_in[1];  // [16,1024,1024,4]
    const float* sigma = (const float*)d_in[2];  // [4]
    float* out = (float*)d_out;

    cudaFuncSetAttribute(gram_kernel, cudaFuncAttributeMaxDynamicSharedMemorySize, GRAM_SMEM);
    cudaFuncSetAttribute(stream_kernel, cudaFuncAttributeMaxDynamicSharedMemorySize, STREAM_SMEM);

    prep_kernel<<<NB * NT / 16, 256>>>(z);
    gram_kernel<<<dim3(NPAIR, 1, NB), 256, GRAM_SMEM>>>();
    stream_kernel<<<NSTREAM_CTA, 256, STREAM_SMEM>>>(gt, sigma, out);
}

// round 15
// speedup vs baseline: 1.3279x; 1.3279x over previous
#include <cuda_runtime.h>
#include <cuda_bf16.h>
#include <cstdint>
#include <cstddef>

// Problem constants
#define NB 16
#define NT 1024
#define ND 256
// DS = 4

#define BM 128
#define LDSK 136       // bf16 elems per A/B smem row for K=128 chunk (272B, odd 16B stride -> ldmatrix conflict-free)
#define GS_STRIDE 130  // bf16 stride of G staging tile (odd word stride -> conflict-free column reads)

#define GRAM_SMEM (2 * 128 * LDSK * 2)   // 69632 B (~68 KB) -> 2 CTAs/SM

#define NTILE (NT / BM)                 // 8
#define NPAIR (NTILE * (NTILE + 1) / 2) // 36
#define NPART (NB * NPAIR)
#define NSTREAM_CTA 2048                // 8 warps/CTA, 1 (b,t) row per warp

// Scratch (no allocations allowed -> __device__ globals)
__device__ __align__(16) __nv_bfloat16 g_zbf[NB * NT * ND];        // 8.4 MB
__device__ __align__(16) __nv_bfloat16 g_G[(size_t)NB * NT * NT];  // 33.5 MB
__device__ float  g_z2[NB * NT];
__device__ double g_partial[NSTREAM_CTA];
__device__ unsigned int g_count;   // zero-init; self-resets each run (graph-replay safe)

// pair p -> (i,j), i<=j, over 8 tiles
__constant__ int PAIR_I[NPAIR] = {0,0,0,0,0,0,0,0, 1,1,1,1,1,1,1, 2,2,2,2,2,2,
                                  3,3,3,3,3, 4,4,4,4, 5,5,5, 6,6, 7};
__constant__ int PAIR_J[NPAIR] = {0,1,2,3,4,5,6,7, 1,2,3,4,5,6,7, 2,3,4,5,6,7,
                                  3,4,5,6,7, 4,5,6,7, 5,6,7, 6,7, 7};

// ---------------------------------------------------------------------------
// Kernel 0 (R1-proven): z -> bf16 + per-row sum of squares. 2 rows/warp.
// ---------------------------------------------------------------------------
__global__ void prep_kernel(const float* __restrict__ z) {
    const int warp = blockIdx.x * 8 + (threadIdx.x >> 5);
    const int lane = threadIdx.x & 31;
    const int row0 = warp * 2;

    const float4* zr0 = reinterpret_cast<const float4*>(z) + (size_t)row0 * (ND / 4);
    const float4* zr1 = zr0 + (ND / 4);
    float4 a0 = zr0[lane];
    float4 a1 = zr0[lane + 32];
    float4 b0 = zr1[lane];
    float4 b1 = zr1[lane + 32];

    float s0 = a0.x*a0.x + a0.y*a0.y + a0.z*a0.z + a0.w*a0.w
             + a1.x*a1.x + a1.y*a1.y + a1.z*a1.z + a1.w*a1.w;
    float s1 = b0.x*b0.x + b0.y*b0.y + b0.z*b0.z + b0.w*b0.w
             + b1.x*b1.x + b1.y*b1.y + b1.z*b1.z + b1.w*b1.w;
    #pragma unroll
    for (int o = 16; o; o >>= 1) {
        s0 += __shfl_xor_sync(0xffffffffu, s0, o);
        s1 += __shfl_xor_sync(0xffffffffu, s1, o);
    }
    if (lane == 0) { g_z2[row0] = s0; g_z2[row0 + 1] = s1; }

    uint2* d0 = reinterpret_cast<uint2*>(g_zbf + (size_t)row0 * ND);
    uint2* d1 = d0 + (ND / 4);
    auto pack = [](float4 v) {
        __nv_bfloat162 lo = __floats2bfloat162_rn(v.x, v.y);
        __nv_bfloat162 hi = __floats2bfloat162_rn(v.z, v.w);
        uint2 p;
        p.x = *reinterpret_cast<uint32_t*>(&lo);
        p.y = *reinterpret_cast<uint32_t*>(&hi);
        return p;
    };
    d0[lane]      = pack(a0);
    d0[lane + 32] = pack(a1);
    d1[lane]      = pack(b0);
    d1[lane + 32] = pack(b1);
}

// ---------------------------------------------------------------------------
// gram_kernel (unchanged, proven): one CTA per (batch, tile pair i<=j).
// ---------------------------------------------------------------------------
#define LDSM4(r0, r1, r2, r3, addr)                                              \
    asm volatile("ldmatrix.sync.aligned.m8n8.x4.shared.b16 {%0,%1,%2,%3}, [%4];" \
                 : "=r"(r0), "=r"(r1), "=r"(r2), "=r"(r3) : "r"(addr))

#define MMA16816(d, a, b0r, b1r)                                                 \
    asm volatile("mma.sync.aligned.m16n8k16.row.col.f32.bf16.bf16.f32 "          \
                 "{%0,%1,%2,%3}, {%4,%5,%6,%7}, {%8,%9}, {%0,%1,%2,%3};"         \
                 : "+f"(d[0]), "+f"(d[1]), "+f"(d[2]), "+f"(d[3])                \
                 : "r"(a[0]), "r"(a[1]), "r"(a[2]), "r"(a[3]), "r"(b0r), "r"(b1r))

__global__ void __launch_bounds__(256, 2)
gram_kernel() {
    extern __shared__ __align__(16) char sm[];
    __nv_bfloat16* As = reinterpret_cast<__nv_bfloat16*>(sm);
    __nv_bfloat16* Bs = reinterpret_cast<__nv_bfloat16*>(sm + 128 * LDSK * 2);
    __nv_bfloat16* Gst = reinterpret_cast<__nv_bfloat16*>(sm);  // overlays A after GEMM

    const int bb = blockIdx.z;
    const int ti = PAIR_I[blockIdx.x];
    const int tj = PAIR_J[blockIdx.x];
    const int tid = threadIdx.x;
    const int lane = tid & 31;
    const int wid  = tid >> 5;

    const int wm = (wid & 3) * 32;
    const int wn = (wid >> 2) * 64;

    float acc[2][8][4];
    #pragma unroll
    for (int mi = 0; mi < 2; mi++)
        #pragma unroll
        for (int ni = 0; ni < 8; ni++)
            #pragma unroll
            for (int r = 0; r < 4; r++) acc[mi][ni][r] = 0.f;

    const uint32_t aBase = (uint32_t)__cvta_generic_to_shared(As);
    const uint32_t bBase = (uint32_t)__cvta_generic_to_shared(Bs);
    const uint32_t aAddr0 = aBase + (((wm + (lane & 15)) * LDSK + (lane >> 4) * 8)) * 2;
    const uint32_t bAddr0 = bBase + (((wn + (lane & 7) + ((lane >> 4) << 3)) * LDSK
                                     + ((lane >> 3) & 1) * 8)) * 2;

    const int4* gzt = reinterpret_cast<const int4*>(g_zbf + ((size_t)bb * NT + ti * BM) * ND);
    const int4* gzs = reinterpret_cast<const int4*>(g_zbf + ((size_t)bb * NT + tj * BM) * ND);

    #pragma unroll
    for (int kc = 0; kc < 2; kc++) {
        #pragma unroll
        for (int i = 0; i < 8; i++) {
            int idx = tid + i * 256;          // 0..2047
            int r = idx >> 4, c = idx & 15;
            *reinterpret_cast<int4*>(As + r * LDSK + c * 8) = gzt[r * 32 + kc * 16 + c];
            *reinterpret_cast<int4*>(Bs + r * LDSK + c * 8) = gzs[r * 32 + kc * 16 + c];
        }
        __syncthreads();

        #pragma unroll
        for (int kk = 0; kk < 8; kk++) {
            uint32_t a[2][4];
            #pragma unroll
            for (int mi = 0; mi < 2; mi++) {
                uint32_t addr = aAddr0 + (uint32_t)(mi * 16 * LDSK * 2) + (uint32_t)(kk * 32);
                LDSM4(a[mi][0], a[mi][1], a[mi][2], a[mi][3], addr);
            }
            uint32_t bf[8][2];
            #pragma unroll
            for (int nj = 0; nj < 4; nj++) {
                uint32_t addr = bAddr0 + (uint32_t)(nj * 16 * LDSK * 2) + (uint32_t)(kk * 32);
                uint32_t r0, r1, r2, r3;
                LDSM4(r0, r1, r2, r3, addr);
                bf[2 * nj][0] = r0;     bf[2 * nj][1] = r1;
                bf[2 * nj + 1][0] = r2; bf[2 * nj + 1][1] = r3;
            }
            #pragma unroll
            for (int mi = 0; mi < 2; mi++)
                #pragma unroll
                for (int ni = 0; ni < 8; ni++)
                    MMA16816(acc[mi][ni], a[mi], bf[ni][0], bf[ni][1]);
        }
        __syncthreads();
    }

    // ---- write G(ti,tj) rows from fragments; stage for transpose ----
    const int rowc = lane >> 2;
    const int colc = (lane & 3) * 2;
    #pragma unroll
    for (int mi = 0; mi < 2; mi++)
        #pragma unroll
        for (int h = 0; h < 2; h++) {
            const int row = wm + mi * 16 + rowc + h * 8;
            #pragma unroll
            for (int ni = 0; ni < 8; ni++) {
                const int col = wn + ni * 8 + colc;
                __nv_bfloat162 v = __floats2bfloat162_rn(acc[mi][ni][h * 2 + 0],
                                                         acc[mi][ni][h * 2 + 1]);
                *reinterpret_cast<__nv_bfloat162*>(
                    g_G + ((size_t)(bb * NT + ti * BM + row)) * NT + tj * BM + col) = v;
                if (ti != tj)
                    *reinterpret_cast<__nv_bfloat162*>(Gst + row * GS_STRIDE + col) = v;
            }
        }

    // ---- transpose write G(tj,ti) from staged tile ----
    if (ti != tj) {
        __syncthreads();
        #pragma unroll
        for (int i = 0; i < 8; i++) {
            int idx = tid + i * 256;          // 0..2047
            int rp = idx >> 4, c16 = idx & 15;
            __align__(16) __nv_bfloat16 v[8];
            #pragma unroll
            for (int k = 0; k < 8; k++)
                v[k] = Gst[(c16 * 8 + k) * GS_STRIDE + rp];
            *reinterpret_cast<uint4*>(
                g_G + ((size_t)(bb * NT + tj * BM + rp)) * NT + ti * BM + c16 * 8)
                = *reinterpret_cast<uint4*>(v);
        }
    }
}

// ---------------------------------------------------------------------------
// Fast exp via exp2 polynomial on the FMA pipe (no MUFU).
// Input y = x*log2(e) precomputed (log2e folded into sigma constants).
// k = round(y) via 1.5*2^23 magic; 2^f by degree-5 Taylor-in-ln2, |f|<=0.5
// (rel err ~2e-6); scale by 2^k via exponent-bit construction.
// ---------------------------------------------------------------------------
__device__ __forceinline__ float exp2_fma(float y) {
    const float MAGIC = 12582912.0f;           // 1.5 * 2^23
    float t = y + MAGIC;
    int   ki = __float_as_int(t) - __float_as_int(MAGIC);
    float f = y - (t - MAGIC);                 // f in [-0.5, 0.5]
    float p = 0.0013333558f;
    p = fmaf(p, f, 0.0096181291f);
    p = fmaf(p, f, 0.0555041087f);
    p = fmaf(p, f, 0.2402265069f);
    p = fmaf(p, f, 0.6931471806f);
    p = fmaf(p, f, 1.0f);
    float scale = __int_as_float((ki + 127) << 23);
    return p * scale;
}

// ---------------------------------------------------------------------------
// stream_kernel (R13 structure): coalesced streamer + smem-staged G +
// fused last-block finalize. Only change vs R13: __expf -> exp2_fma (FMA pipe),
// with log2(e) folded into the sigma constants.
// ---------------------------------------------------------------------------
__global__ void __launch_bounds__(256)
stream_kernel(const float* __restrict__ gt, const float* __restrict__ sigma,
              float* __restrict__ out) {
    __shared__ __align__(16) unsigned short sG[8][1024];   // 16 KB
    const int tid = threadIdx.x;
    const int lane = tid & 31;
    const int wid  = tid >> 5;
    const int bt = blockIdx.x * 8 + wid;      // 0..16383
    const int b = bt >> 10, t = bt & 1023;

    const float LOG2E = 1.4426950408889634f;
    const float sg0 = sigma[0], sg1 = sigma[1], sg2 = sigma[2], sg3 = sigma[3];
    const float inv0 = LOG2E / (2.0f * sg0 * sg0);
    const float inv1 = LOG2E / (2.0f * sg1 * sg1);
    const float inv2 = LOG2E / (2.0f * sg2 * sg2);
    const float inv3 = LOG2E / (2.0f * sg3 * sg3);

    const size_t rowbase = ((size_t)b * NT + t) * NT;
    const float4* gp = reinterpret_cast<const float4*>(gt) + rowbase + lane;
    const float z2t = g_z2[b * NT + t];

    // ---- stage this warp's G row (2 KB) into smem, coalesced ----
    {
        const uint4* Gv4 = reinterpret_cast<const uint4*>(g_G + rowbase);
        uint4 q[4];
        #pragma unroll
        for (int it = 0; it < 4; it++) q[it] = Gv4[lane + it * 32];
        #pragma unroll
        for (int it = 0; it < 4; it++)
            reinterpret_cast<uint4*>(sG[wid])[lane + it * 32] = q[it];
    }
    __syncwarp();

    float part = 0.f;
    #pragma unroll
    for (int c = 0; c < 4; c++) {
        float4 g[8];
        #pragma unroll
        for (int u = 0; u < 8; u++)
            g[u] = __ldcs(gp + (c * 8 + u) * 32);
        #pragma unroll
        for (int u = 0; u < 8; u++) {
            float y = g[u].x * g[u].x * inv0 + g[u].y * g[u].y * inv1
                    + g[u].z * g[u].z * inv2 + g[u].w * g[u].w * inv3;
            float w = exp2_fma(y);
            unsigned short Gq = sG[wid][lane + (c * 8 + u) * 32];
            float Gv = __bfloat162float(*reinterpret_cast<__nv_bfloat16*>(&Gq));
            part += w * (z2t - Gv);
        }
    }

    // ---- CTA reduction (deterministic) ----
    #pragma unroll
    for (int o = 16; o; o >>= 1) part += __shfl_xor_sync(0xffffffffu, part, o);
    __shared__ double red[8];
    if (lane == 0) red[wid] = (double)part;
    __syncthreads();
    if (tid == 0) {
        double ssum = 0.0;
        #pragma unroll
        for (int i = 0; i < 8; i++) ssum += red[i];
        g_partial[blockIdx.x] = ssum;
    }

    // ---- fused finalize: last CTA reduces all partials in fixed order ----
    __shared__ bool isLast;
    __threadfence();
    if (tid == 0) {
        unsigned int c = atomicAdd(&g_count, 1u);
        isLast = (c == (unsigned int)(gridDim.x - 1));
    }
    __syncthreads();
    if (isLast) {
        __shared__ double fred[256];
        double v = 0.0;
        for (int i = tid; i < NSTREAM_CTA; i += 256) v += g_partial[i];
        fred[tid] = v;
        __syncthreads();
        for (int off = 128; off; off >>= 1) {
            if (tid < off) fred[tid] += fred[tid + off];
            __syncthreads();
        }
        if (tid == 0) {
            out[0] = (float)(fred[0] * (2.0 / ((double)NB * (double)NT * (double)NT)));
            g_count = 0;   // reset for next graph replay
        }
    }
}

// ---------------------------------------------------------------------------
extern "C" void kernel_launch(void* const* d_in, const int* in_sizes, int n_in,
                              void* d_out, int out_size) {
    const float* z     = (const float*)d_in[0];  // [16,1024,256]
    const float* gt    = (const float*)d_in[1];  // [16,1024,1024,4]
    const float* sigma = (const float*)d_in[2];  // [4]
    float* out = (float*)d_out;

    cudaFuncSetAttribute(gram_kernel, cudaFuncAttributeMaxDynamicSharedMemorySize, GRAM_SMEM);

    prep_kernel<<<NB * NT / 16, 256>>>(z);
    gram_kernel<<<dim3(NPAIR, 1, NB), 256, GRAM_SMEM>>>();
    stream_kernel<<<NSTREAM_CTA, 256>>>(gt, sigma, out);
}